// round 14
// baseline (speedup 1.0000x reference)
#include <cuda_runtime.h>
#include <cuda_fp16.h>
#include <cuda.h>
#include <math.h>
#include <stdint.h>

// ---------------- problem constants ----------------
#define B_ 2048
#define D_ 512
#define C_ 50000
#define NPAD_ 50048      // 391 * 128, zero-padded class rows

__device__ __constant__ float kCOS_M = 0.86602540378443864676f; // cos(pi/6)
__device__ __constant__ float kSIN_M = 0.5f;                    // sin(pi/6)
__device__ __constant__ float kTH    = -0.86602540378443864676f;// cos(pi - m)
__device__ __constant__ float kMM    = 0.26179938779914943654f; // sin(pi-m)*m
#define S_SCALE 15.0f
#define EPS_ 1e-12f

// ---------------- scratch (static device globals; no allocation) ------------
__device__ __align__(1024) __half g_xn[B_ * D_];      // 2 MB   normalized x, fp16
__device__ __align__(1024) __half g_wn[NPAD_ * D_];   // 51.25 MB normalized W, fp16
__device__ float g_expsum[B_];
__device__ int   g_label[B_];

// ---------------- device helpers ----------------
__device__ __forceinline__ uint32_t smem_u32(const void* p) {
    return (uint32_t)__cvta_generic_to_shared(p);
}
__device__ __forceinline__ void ldm4(uint32_t r[4], uint32_t addr) {
    asm volatile("ldmatrix.sync.aligned.m8n8.x4.shared.b16 {%0,%1,%2,%3}, [%4];"
                 : "=r"(r[0]), "=r"(r[1]), "=r"(r[2]), "=r"(r[3]) : "r"(addr));
}
// f16-accumulate HMMA: D(f16x2 pair) += A*B
__device__ __forceinline__ void mma16816h(uint32_t c[2], const uint32_t a[4],
                                          uint32_t b0, uint32_t b1) {
    asm volatile(
        "mma.sync.aligned.m16n8k16.row.col.f16.f16.f16.f16 "
        "{%0,%1}, {%2,%3,%4,%5}, {%6,%7}, {%0,%1};"
        : "+r"(c[0]), "+r"(c[1])
        : "r"(a[0]), "r"(a[1]), "r"(a[2]), "r"(a[3]), "r"(b0), "r"(b1));
}

// mbarrier (family-portable sm_90 PTX)
#define MBARRIER_INIT(a, n) \
    asm volatile("mbarrier.init.shared.b64 [%0], %1;" :: "r"(a), "r"((uint32_t)(n)) : "memory")
#define MBARRIER_EXPECT_TX(a, bytes) \
    asm volatile("mbarrier.arrive.expect_tx.shared.b64 _, [%0], %1;" \
                 :: "r"(a), "r"((uint32_t)(bytes)) : "memory")
#define MBARRIER_WAIT_PARITY(mbar_addr, par) do {                               \
    uint32_t _m = (uint32_t)(mbar_addr);                                        \
    uint32_t _p = (uint32_t)(par);                                              \
    uint32_t _done;                                                             \
    asm volatile("{\n\t.reg .pred p;\n\t"                                       \
        "mbarrier.try_wait.parity.acquire.cta.shared::cta.b64 p, [%1], %2;\n\t" \
        "selp.b32 %0, 1, 0, p;\n\t}" : "=r"(_done) : "r"(_m), "r"(_p) : "memory"); \
    if (!_done) {                                                               \
        asm volatile("{\n\t.reg .pred P1;\n\t"                                  \
        "WL_%=:\n\t"                                                            \
        "mbarrier.try_wait.parity.acquire.cta.shared::cta.b64 P1, [%0], %1, 0x989680;\n\t" \
        "@P1 bra.uni WD_%=;\n\t"                                                \
        "bra.uni WL_%=;\n\t"                                                    \
        "WD_%=:\n\t}" :: "r"(_m), "r"(_p) : "memory");                          \
    }                                                                           \
} while (0)

// 2D TMA load into shared, mbarrier completion (sm_90 family-portable)
#define TMA_LOAD_2D(smem_addr, map_ptr, cx, cy, mbar) \
    asm volatile( \
        "cp.async.bulk.tensor.2d.shared::cluster.global.tile.mbarrier::complete_tx::bytes " \
        "[%0], [%1, {%2, %3}], [%4];" \
        :: "r"((uint32_t)(smem_addr)), "l"(map_ptr), "r"((int)(cx)), "r"((int)(cy)), \
           "r"((uint32_t)(mbar)) : "memory")

// FMA-pipe exp (poly exp2); valid |x| < 80, rel err ~1e-7.
__device__ __forceinline__ float fexp_poly(float x) {
    float u  = x * 1.44269504088896341f;
    float kf = floorf(u);
    float f  = u - kf;
    float p  = 0.00133335581f;
    p = fmaf(p, f, 0.00961812911f);
    p = fmaf(p, f, 0.05550410866f);
    p = fmaf(p, f, 0.24022650696f);
    p = fmaf(p, f, 0.69314718056f);
    p = fmaf(p, f, 1.0f);
    float sc = __int_as_float(((int)kf + 127) << 23);
    return p * sc;
}

// ---------------- labels: dtype probe + extract + expsum zero (1 block) -----
__global__ void label_kernel(const void* lab) {
    __shared__ int red[256];
    const int* lab32 = (const int*)lab;
    int acc = 0;
    for (int i = 2 * threadIdx.x + 1; i < 2048; i += 512) acc |= lab32[i];
    red[threadIdx.x] = acc;
    __syncthreads();
    for (int s = 128; s > 0; s >>= 1) {
        if (threadIdx.x < s) red[threadIdx.x] |= red[threadIdx.x + s];
        __syncthreads();
    }
    const int is64 = (red[0] == 0);
    for (int i = threadIdx.x; i < B_; i += 256) {
        g_label[i]  = is64 ? (int)((const long long*)lab)[i] : lab32[i];
        g_expsum[i] = 0.f;
    }
}

// ---------------- normalize -> fp16 (warp per row) ----------------
__global__ void norm_x_kernel(const float* __restrict__ x) {
    const int row  = blockIdx.x * 8 + (threadIdx.x >> 5);
    const int lane = threadIdx.x & 31;
    const float4* src = (const float4*)(x + (size_t)row * D_);
    float4 v[4];
    float ss = 0.f;
    #pragma unroll
    for (int q = 0; q < 4; q++) {
        v[q] = src[lane + 32 * q];
        ss += v[q].x * v[q].x + v[q].y * v[q].y + v[q].z * v[q].z + v[q].w * v[q].w;
    }
    #pragma unroll
    for (int o = 16; o > 0; o >>= 1) ss += __shfl_xor_sync(0xffffffffu, ss, o);
    float inv = 1.0f / fmaxf(sqrtf(ss), EPS_);
    uint2* dst = (uint2*)(g_xn + (size_t)row * D_);
    #pragma unroll
    for (int q = 0; q < 4; q++) {
        __half2 h01 = __floats2half2_rn(v[q].x * inv, v[q].y * inv);
        __half2 h23 = __floats2half2_rn(v[q].z * inv, v[q].w * inv);
        uint2 pk;
        pk.x = *(uint32_t*)&h01;
        pk.y = *(uint32_t*)&h23;
        dst[lane + 32 * q] = pk;
    }
}

__global__ void norm_w_kernel(const float* __restrict__ w) {
    const int row  = blockIdx.x * 8 + (threadIdx.x >> 5);
    const int lane = threadIdx.x & 31;
    uint2* dst = (uint2*)(g_wn + (size_t)row * D_);
    if (row >= C_) {
        uint2 z = make_uint2(0u, 0u);
        #pragma unroll
        for (int q = 0; q < 4; q++) dst[lane + 32 * q] = z;
        return;
    }
    const float4* src = (const float4*)(w + (size_t)row * D_);
    float4 v[4];
    float ss = 0.f;
    #pragma unroll
    for (int q = 0; q < 4; q++) {
        v[q] = src[lane + 32 * q];
        ss += v[q].x * v[q].x + v[q].y * v[q].y + v[q].z * v[q].z + v[q].w * v[q].w;
    }
    #pragma unroll
    for (int o = 16; o > 0; o >>= 1) ss += __shfl_xor_sync(0xffffffffu, ss, o);
    float inv = 1.0f / fmaxf(sqrtf(ss), EPS_);
    #pragma unroll
    for (int q = 0; q < 4; q++) {
        __half2 h01 = __floats2half2_rn(v[q].x * inv, v[q].y * inv);
        __half2 h23 = __floats2half2_rn(v[q].z * inv, v[q].w * inv);
        uint2 pk;
        pk.x = *(uint32_t*)&h01;
        pk.y = *(uint32_t*)&h23;
        dst[lane + 32 * q] = pk;
    }
}

// ---------------- TMA-fed mma.sync fp16 GEMM + fused epilogue ----------------
// CTA tile 128x128, 8 warps each 64x32, BK=64, 2 TMA stages.
// f16-ACCUMULATE HMMA in two chunk sets (k<256 -> accA, k>=256 -> accB),
// promoted to fp32 in the epilogue. Reg count unchanged (~126) -> 2 CTA/SM.
#define SMEM_CTRL   1024
#define STAGE_BYTES 32768
#define BMAT_OFF    16384
#define GEMM_SMEM   (SMEM_CTRL + 2 * STAGE_BYTES)

__global__ void __launch_bounds__(256, 2) gemm_mma_kernel(
        float* __restrict__ out,
        const __grid_constant__ CUtensorMap tmA,
        const __grid_constant__ CUtensorMap tmB) {
    extern __shared__ __align__(1024) char smem[];
    const uint32_t sb = smem_u32(smem);
    const uint32_t stage0 = sb + SMEM_CTRL;
    const int tid  = threadIdx.x;
    const int lane = tid & 31;
    const int w    = tid >> 5;
    const int wm   = w & 1;        // 2 warp-rows  (64 m each)
    const int wn   = w >> 1;       // 4 warp-cols  (32 n each)
    const int m0   = blockIdx.x * 128;   // m inner -> B tiles shared via L2
    const int n0   = blockIdx.y * 128;

    if (tid == 0) {
        MBARRIER_INIT(sb + 0, 1);
        MBARRIER_INIT(sb + 8, 1);
    }
    __syncthreads();

    // prologue: fill both stages (k-chunks 0, 1)
    if (tid == 0) {
        MBARRIER_EXPECT_TX(sb + 0, 2 * 16384);
        TMA_LOAD_2D(stage0,            &tmA, 0, m0, sb + 0);
        TMA_LOAD_2D(stage0 + BMAT_OFF, &tmB, 0, n0, sb + 0);
        MBARRIER_EXPECT_TX(sb + 8, 2 * 16384);
        TMA_LOAD_2D(stage0 + STAGE_BYTES,            &tmA, 64, m0, sb + 8);
        TMA_LOAD_2D(stage0 + STAGE_BYTES + BMAT_OFF, &tmB, 64, n0, sb + 8);
    }

    // two f16x2 accumulator sets (each 32 regs)
    uint32_t accA[4][4][2];
    uint32_t accB[4][4][2];
    #pragma unroll
    for (int i = 0; i < 4; i++)
        #pragma unroll
        for (int j = 0; j < 4; j++) {
            accA[i][j][0] = 0u; accA[i][j][1] = 0u;
            accB[i][j][0] = 0u; accB[i][j][1] = 0u;
        }

    // ---- fragment addressing (constant per thread)
    const int rowA   = wm * 64 + (lane & 15);
    const int ax     = rowA & 7;
    const int laneHi = lane >> 4;
    const uint32_t aRow = (uint32_t)rowA * 128u;
    const int nrowB = wn * 32 + ((lane >> 4) << 3) + (lane & 7);
    const int bx    = nrowB & 7;
    const int cbit  = (lane >> 3) & 1;
    const uint32_t bRow = (uint32_t)nrowB * 128u + BMAT_OFF;

    int ph0 = 0, ph1 = 0;

#define K_ITER_BODY(ACC, KI) {                                                  \
        const int s_ = (KI) & 1;                                                \
        if (s_ == 0) { MBARRIER_WAIT_PARITY(sb + 0, ph0); ph0 ^= 1; }           \
        else         { MBARRIER_WAIT_PARITY(sb + 8, ph1); ph1 ^= 1; }           \
        const uint32_t st = stage0 + (uint32_t)s_ * STAGE_BYTES;                \
        _Pragma("unroll")                                                       \
        for (int kk = 0; kk < 4; kk++) {                                        \
            const int chA = kk * 2 + laneHi;                                    \
            const uint32_t slotA = (uint32_t)((chA ^ ax) << 4);                 \
            uint32_t ah[4][4];                                                  \
            _Pragma("unroll")                                                   \
            for (int i = 0; i < 4; i++)                                         \
                ldm4(ah[i], st + aRow + i * 2048 + slotA);                      \
            const int chB = kk * 2 + cbit;                                      \
            const uint32_t slotB = (uint32_t)((chB ^ bx) << 4);                 \
            uint32_t bh[4][2];                                                  \
            _Pragma("unroll")                                                   \
            for (int pp = 0; pp < 2; pp++) {                                    \
                uint32_t tb[4];                                                 \
                ldm4(tb, st + bRow + pp * 2048 + slotB);                        \
                bh[2 * pp][0] = tb[0]; bh[2 * pp][1] = tb[1];                   \
                bh[2 * pp + 1][0] = tb[2]; bh[2 * pp + 1][1] = tb[3];           \
            }                                                                   \
            _Pragma("unroll")                                                   \
            for (int i = 0; i < 4; i++)                                         \
                _Pragma("unroll")                                               \
                for (int jj = 0; jj < 4; jj++)                                  \
                    mma16816h(ACC[i][jj], ah[i], bh[jj][0], bh[jj][1]);         \
        }                                                                       \
        __syncthreads();                                                        \
        if ((KI) + 2 < 8 && tid == 0) {                                         \
            const uint32_t mb = sb + (uint32_t)s_ * 8;                          \
            MBARRIER_EXPECT_TX(mb, 2 * 16384);                                  \
            TMA_LOAD_2D(st,            &tmA, ((KI) + 2) * 64, m0, mb);          \
            TMA_LOAD_2D(st + BMAT_OFF, &tmB, ((KI) + 2) * 64, n0, mb);          \
        }                                                                       \
    }

    for (int ki = 0; ki < 4; ki++) K_ITER_BODY(accA, ki);
    for (int ki = 4; ki < 8; ki++) K_ITER_BODY(accB, ki);

    // ---- epilogue: promote f16 chunk sums to fp32, margin, store, expsum
    float es[4][2];
    #pragma unroll
    for (int i = 0; i < 4; i++) { es[i][0] = 0.f; es[i][1] = 0.f; }

    #pragma unroll
    for (int i = 0; i < 4; i++) {
        const int r0 = m0 + wm * 64 + i * 16 + (lane >> 2);
        const int r1 = r0 + 8;
        const int lab0 = g_label[r0];
        const int lab1 = g_label[r1];
        float* const o0 = out + (size_t)r0 * C_;
        float* const o1 = out + (size_t)r1 * C_;
        #pragma unroll
        for (int j = 0; j < 4; j++) {
            const int col = n0 + wn * 32 + j * 8 + (lane & 3) * 2;
            if (col < C_) {
                // promote: acc[q] = accA + accB in fp32
                float2 fa01 = __half22float2(*(__half2*)&accA[i][j][0]);
                float2 fb01 = __half22float2(*(__half2*)&accB[i][j][0]);
                float2 fa23 = __half22float2(*(__half2*)&accA[i][j][1]);
                float2 fb23 = __half22float2(*(__half2*)&accB[i][j][1]);
                float cc[4];
                cc[0] = fa01.x + fb01.x;
                cc[1] = fa01.y + fb01.y;
                cc[2] = fa23.x + fb23.x;
                cc[3] = fa23.y + fb23.y;

                float2 v0, v1;
                float* p0 = (float*)&v0;
                float* p1 = (float*)&v1;
                #pragma unroll
                for (int q = 0; q < 2; q++) {
                    float c = cc[q];
                    if (col + q == lab0) {
                        float st2 = sqrtf(fmaxf(1.f - c * c, 0.f));
                        float phi = c * kCOS_M - st2 * kSIN_M;
                        c = (c - kTH > 0.f) ? phi : (c - kMM);
                    }
                    p0[q] = S_SCALE * c;
                    float d = cc[q + 2];
                    if (col + q == lab1) {
                        float st2 = sqrtf(fmaxf(1.f - d * d, 0.f));
                        float phi = d * kCOS_M - st2 * kSIN_M;
                        d = (d - kTH > 0.f) ? phi : (d - kMM);
                    }
                    p1[q] = S_SCALE * d;
                }
                __stcs(reinterpret_cast<float2*>(o0 + col), v0);
                __stcs(reinterpret_cast<float2*>(o1 + col), v1);
                es[i][0] += fexp_poly(p0[0]) + fexp_poly(p0[1]);
                es[i][1] += fexp_poly(p1[0]) + fexp_poly(p1[1]);
            }
        }
    }
    #pragma unroll
    for (int i = 0; i < 4; i++) {
        #pragma unroll
        for (int h = 0; h < 2; h++) {
            float v = es[i][h];
            v += __shfl_xor_sync(0xffffffffu, v, 1);
            v += __shfl_xor_sync(0xffffffffu, v, 2);
            if ((lane & 3) == 0) {
                const int r = m0 + wm * 64 + i * 16 + h * 8 + (lane >> 2);
                atomicAdd(&g_expsum[r], v);
            }
        }
    }
}

// ---------------- loss finalize (expsum accumulated in GEMM epilogue) -------
__global__ void finalize_kernel(float* __restrict__ out, int out_size) {
    __shared__ float red[256];
    float a = 0.f;
    for (int r = threadIdx.x; r < B_; r += 256) {
        float tgt = out[(size_t)r * C_ + g_label[r]];
        a += logf(g_expsum[r]) - tgt;
    }
    red[threadIdx.x] = a;
    __syncthreads();
    for (int s = 128; s > 0; s >>= 1) {
        if (threadIdx.x < s) red[threadIdx.x] += red[threadIdx.x + s];
        __syncthreads();
    }
    if (threadIdx.x == 0) {
        float loss = red[0] / (float)B_;
        for (long long i = (long long)B_ * C_; i < (long long)out_size; i++)
            out[i] = loss;
    }
}

// ---------------- host: tensor-map encode via driver entry point ------------
typedef CUresult (*tmap_encode_fn_t)(
    CUtensorMap*, CUtensorMapDataType, cuuint32_t, void*,
    const cuuint64_t*, const cuuint64_t*, const cuuint32_t*, const cuuint32_t*,
    CUtensorMapInterleave, CUtensorMapSwizzle, CUtensorMapL2promotion,
    CUtensorMapFloatOOBfill);

static tmap_encode_fn_t get_encode_fn() {
    void* fn = nullptr;
    cudaDriverEntryPointQueryResult qr;
#if CUDART_VERSION >= 12050
    cudaGetDriverEntryPointByVersion("cuTensorMapEncodeTiled", &fn, 12000,
                                     cudaEnableDefault, &qr);
#else
    cudaGetDriverEntryPoint("cuTensorMapEncodeTiled", &fn, cudaEnableDefault, &qr);
#endif
    return (tmap_encode_fn_t)fn;
}

static void encode_map(tmap_encode_fn_t enc, CUtensorMap* tm, void* base,
                       unsigned long long rows) {
    cuuint64_t dims[2]    = {(cuuint64_t)D_, (cuuint64_t)rows};
    cuuint64_t strides[1] = {(cuuint64_t)(D_ * 2)};      // 1024 B/row
    cuuint32_t box[2]     = {64, 128};                   // 128B x 128 rows
    cuuint32_t estr[2]    = {1, 1};
    enc(tm, CU_TENSOR_MAP_DATA_TYPE_FLOAT16, 2, base, dims, strides, box, estr,
        CU_TENSOR_MAP_INTERLEAVE_NONE, CU_TENSOR_MAP_SWIZZLE_128B,
        CU_TENSOR_MAP_L2_PROMOTION_L2_128B, CU_TENSOR_MAP_FLOAT_OOB_FILL_NONE);
}

// ---------------- launch ----------------
extern "C" void kernel_launch(void* const* d_in, const int* in_sizes, int n_in,
                              void* d_out, int out_size) {
    const float* x   = (const float*)d_in[0];
    const void*  lab = d_in[1];
    const float* w   = (const float*)d_in[2];
    float* out = (float*)d_out;

    cudaFuncSetAttribute(gemm_mma_kernel,
                         cudaFuncAttributeMaxDynamicSharedMemorySize, GEMM_SMEM);

    // tensor maps (host-side, deterministic, no allocation)
    tmap_encode_fn_t enc = get_encode_fn();
    void *dA = nullptr, *dB = nullptr;
    cudaGetSymbolAddress(&dA, g_xn);
    cudaGetSymbolAddress(&dB, g_wn);
    CUtensorMap tmA, tmB;
    encode_map(enc, &tmA, dA, B_);
    encode_map(enc, &tmB, dB, NPAD_);

    label_kernel<<<1, 256>>>(lab);
    norm_x_kernel<<<B_ / 8, 256>>>(x);
    norm_w_kernel<<<NPAD_ / 8, 256>>>(w);

    dim3 grid(B_ / 128, NPAD_ / 128);   // (16, 391), m inner
    gemm_mma_kernel<<<grid, 256, GEMM_SMEM>>>(out, tmA, tmB);

    finalize_kernel<<<1, 256>>>(out, out_size);
}

// round 15
// speedup vs baseline: 1.5078x; 1.5078x over previous
#include <cuda_runtime.h>
#include <cuda_fp16.h>
#include <cuda.h>
#include <math.h>
#include <stdint.h>

// ---------------- problem constants ----------------
#define B_ 2048
#define D_ 512
#define C_ 50000
#define NPAD_ 50048      // 391 * 128, zero-padded class rows

__device__ __constant__ float kCOS_M = 0.86602540378443864676f; // cos(pi/6)
__device__ __constant__ float kSIN_M = 0.5f;                    // sin(pi/6)
__device__ __constant__ float kTH    = -0.86602540378443864676f;// cos(pi - m)
__device__ __constant__ float kMM    = 0.26179938779914943654f; // sin(pi-m)*m
#define S_SCALE 15.0f
#define EPS_ 1e-12f

// ---------------- scratch (static device globals; no allocation) ------------
__device__ __align__(1024) __half g_xn[B_ * D_];      // 2 MB   normalized x, fp16
__device__ __align__(1024) __half g_wn[NPAD_ * D_];   // 51.25 MB normalized W, fp16
__device__ float g_expsum[B_];
__device__ int   g_label[B_];

// ---------------- device helpers ----------------
__device__ __forceinline__ uint32_t smem_u32(const void* p) {
    return (uint32_t)__cvta_generic_to_shared(p);
}
__device__ __forceinline__ void ldm4(uint32_t r[4], uint32_t addr) {
    asm volatile("ldmatrix.sync.aligned.m8n8.x4.shared.b16 {%0,%1,%2,%3}, [%4];"
                 : "=r"(r[0]), "=r"(r[1]), "=r"(r[2]), "=r"(r[3]) : "r"(addr));
}
__device__ __forceinline__ void mma16816(float c[4], const uint32_t a[4],
                                         uint32_t b0, uint32_t b1) {
    asm volatile(
        "mma.sync.aligned.m16n8k16.row.col.f32.f16.f16.f32 "
        "{%0,%1,%2,%3}, {%4,%5,%6,%7}, {%8,%9}, {%0,%1,%2,%3};"
        : "+f"(c[0]), "+f"(c[1]), "+f"(c[2]), "+f"(c[3])
        : "r"(a[0]), "r"(a[1]), "r"(a[2]), "r"(a[3]), "r"(b0), "r"(b1));
}

// mbarrier (family-portable sm_90 PTX)
#define MBARRIER_INIT(a, n) \
    asm volatile("mbarrier.init.shared.b64 [%0], %1;" :: "r"(a), "r"((uint32_t)(n)) : "memory")
#define MBARRIER_EXPECT_TX(a, bytes) \
    asm volatile("mbarrier.arrive.expect_tx.shared.b64 _, [%0], %1;" \
                 :: "r"(a), "r"((uint32_t)(bytes)) : "memory")
#define MBARRIER_WAIT_PARITY(mbar_addr, par) do {                               \
    uint32_t _m = (uint32_t)(mbar_addr);                                        \
    uint32_t _p = (uint32_t)(par);                                              \
    uint32_t _done;                                                             \
    asm volatile("{\n\t.reg .pred p;\n\t"                                       \
        "mbarrier.try_wait.parity.acquire.cta.shared::cta.b64 p, [%1], %2;\n\t" \
        "selp.b32 %0, 1, 0, p;\n\t}" : "=r"(_done) : "r"(_m), "r"(_p) : "memory"); \
    if (!_done) {                                                               \
        asm volatile("{\n\t.reg .pred P1;\n\t"                                  \
        "WL_%=:\n\t"                                                            \
        "mbarrier.try_wait.parity.acquire.cta.shared::cta.b64 P1, [%0], %1, 0x989680;\n\t" \
        "@P1 bra.uni WD_%=;\n\t"                                                \
        "bra.uni WL_%=;\n\t"                                                    \
        "WD_%=:\n\t}" :: "r"(_m), "r"(_p) : "memory");                          \
    }                                                                           \
} while (0)

// 2D TMA load into shared, mbarrier completion (sm_90 family-portable)
#define TMA_LOAD_2D(smem_addr, map_ptr, cx, cy, mbar) \
    asm volatile( \
        "cp.async.bulk.tensor.2d.shared::cluster.global.tile.mbarrier::complete_tx::bytes " \
        "[%0], [%1, {%2, %3}], [%4];" \
        :: "r"((uint32_t)(smem_addr)), "l"(map_ptr), "r"((int)(cx)), "r"((int)(cy)), \
           "r"((uint32_t)(mbar)) : "memory")

// FMA-pipe exp (poly exp2); valid |x| < 80, rel err ~1e-7.
__device__ __forceinline__ float fexp_poly(float x) {
    float u  = x * 1.44269504088896341f;
    float kf = floorf(u);
    float f  = u - kf;
    float p  = 0.00133335581f;
    p = fmaf(p, f, 0.00961812911f);
    p = fmaf(p, f, 0.05550410866f);
    p = fmaf(p, f, 0.24022650696f);
    p = fmaf(p, f, 0.69314718056f);
    p = fmaf(p, f, 1.0f);
    float sc = __int_as_float(((int)kf + 127) << 23);
    return p * sc;
}

// ---------------- normalize x -> fp16 (warp per row) + label handling -------
// Blocks 0..7 additionally probe label dtype (int64 vs int32), extract their
// 256 labels, and zero their slice of g_expsum. Deterministic every launch.
__global__ void norm_x_kernel(const float* __restrict__ x, const void* lab) {
    const int row  = blockIdx.x * 8 + (threadIdx.x >> 5);
    const int lane = threadIdx.x & 31;
    const float4* src = (const float4*)(x + (size_t)row * D_);
    float4 v[4];
    float ss = 0.f;
    #pragma unroll
    for (int q = 0; q < 4; q++) {
        v[q] = __ldcs(src + lane + 32 * q);
        ss += v[q].x * v[q].x + v[q].y * v[q].y + v[q].z * v[q].z + v[q].w * v[q].w;
    }
    #pragma unroll
    for (int o = 16; o > 0; o >>= 1) ss += __shfl_xor_sync(0xffffffffu, ss, o);
    float inv = 1.0f / fmaxf(sqrtf(ss), EPS_);
    uint2* dst = (uint2*)(g_xn + (size_t)row * D_);
    #pragma unroll
    for (int q = 0; q < 4; q++) {
        __half2 h01 = __floats2half2_rn(v[q].x * inv, v[q].y * inv);
        __half2 h23 = __floats2half2_rn(v[q].z * inv, v[q].w * inv);
        uint2 pk;
        pk.x = *(uint32_t*)&h01;
        pk.y = *(uint32_t*)&h23;
        dst[lane + 32 * q] = pk;
    }

    if (blockIdx.x < 8) {
        // dtype probe: int64 labels (values < 2^32) have all-zero odd words
        __shared__ int red[256];
        const int* lab32 = (const int*)lab;
        int acc = 0;
        for (int i = 2 * threadIdx.x + 1; i < 4096; i += 512) acc |= lab32[i];
        red[threadIdx.x] = acc;
        __syncthreads();
        for (int s = 128; s > 0; s >>= 1) {
            if (threadIdx.x < s) red[threadIdx.x] |= red[threadIdx.x + s];
            __syncthreads();
        }
        const int is64 = (red[0] == 0);
        const int i = blockIdx.x * 256 + threadIdx.x;
        g_label[i]  = is64 ? (int)((const long long*)lab)[i] : lab32[i];
        g_expsum[i] = 0.f;
    }
}

// ---------------- normalize W -> fp16 (warp per row) ----------------
__global__ void norm_w_kernel(const float* __restrict__ w) {
    const int row  = blockIdx.x * 8 + (threadIdx.x >> 5);
    const int lane = threadIdx.x & 31;
    uint2* dst = (uint2*)(g_wn + (size_t)row * D_);
    if (row >= C_) {
        uint2 z = make_uint2(0u, 0u);
        #pragma unroll
        for (int q = 0; q < 4; q++) dst[lane + 32 * q] = z;
        return;
    }
    const float4* src = (const float4*)(w + (size_t)row * D_);
    float4 v[4];
    float ss = 0.f;
    #pragma unroll
    for (int q = 0; q < 4; q++) {
        v[q] = __ldcs(src + lane + 32 * q);   // streaming: don't evict g_wn from L2
        ss += v[q].x * v[q].x + v[q].y * v[q].y + v[q].z * v[q].z + v[q].w * v[q].w;
    }
    #pragma unroll
    for (int o = 16; o > 0; o >>= 1) ss += __shfl_xor_sync(0xffffffffu, ss, o);
    float inv = 1.0f / fmaxf(sqrtf(ss), EPS_);
    #pragma unroll
    for (int q = 0; q < 4; q++) {
        __half2 h01 = __floats2half2_rn(v[q].x * inv, v[q].y * inv);
        __half2 h23 = __floats2half2_rn(v[q].z * inv, v[q].w * inv);
        uint2 pk;
        pk.x = *(uint32_t*)&h01;
        pk.y = *(uint32_t*)&h23;
        dst[lane + 32 * q] = pk;
    }
}

// ---------------- TMA-fed mma.sync fp16 GEMM + fused epilogue (R11) ---------
// CTA tile 128x128, 4 warps each 64x64, BK=64, 2 TMA stages, 128 threads,
// 3 CTA/SM. mma.sync f32-acc at its measured HW floor (~13.4 cyc/HMMA/SMSP).
#define SMEM_CTRL   1024
#define STAGE_BYTES 32768
#define BMAT_OFF    16384
#define GEMM_SMEM   (SMEM_CTRL + 2 * STAGE_BYTES)

__global__ void __launch_bounds__(128, 3) gemm_mma_kernel(
        float* __restrict__ out,
        const __grid_constant__ CUtensorMap tmA,
        const __grid_constant__ CUtensorMap tmB) {
    extern __shared__ __align__(1024) char smem[];
    const uint32_t sb = smem_u32(smem);
    const uint32_t stage0 = sb + SMEM_CTRL;
    const int tid  = threadIdx.x;
    const int lane = tid & 31;
    const int w    = tid >> 5;
    const int wm   = w & 1;        // 2 warp-rows  (64 m each)
    const int wn   = w >> 1;       // 2 warp-cols  (64 n each)
    const int m0   = blockIdx.x * 128;   // m inner -> B tiles shared via L2
    const int n0   = blockIdx.y * 128;

    if (tid == 0) {
        MBARRIER_INIT(sb + 0, 1);
        MBARRIER_INIT(sb + 8, 1);
    }
    __syncthreads();

    // prologue: fill both stages (k-chunks 0, 1)
    if (tid == 0) {
        MBARRIER_EXPECT_TX(sb + 0, 2 * 16384);
        TMA_LOAD_2D(stage0,            &tmA, 0, m0, sb + 0);
        TMA_LOAD_2D(stage0 + BMAT_OFF, &tmB, 0, n0, sb + 0);
        MBARRIER_EXPECT_TX(sb + 8, 2 * 16384);
        TMA_LOAD_2D(stage0 + STAGE_BYTES,            &tmA, 64, m0, sb + 8);
        TMA_LOAD_2D(stage0 + STAGE_BYTES + BMAT_OFF, &tmB, 64, n0, sb + 8);
    }

    float acc[4][8][4];
    #pragma unroll
    for (int i = 0; i < 4; i++)
        #pragma unroll
        for (int j = 0; j < 8; j++)
            #pragma unroll
            for (int q = 0; q < 4; q++) acc[i][j][q] = 0.f;

    // ---- fragment addressing (constant per thread)
    const int rowA   = wm * 64 + (lane & 15);
    const int ax     = rowA & 7;
    const int laneHi = lane >> 4;
    const uint32_t aRow = (uint32_t)rowA * 128u;
    const int nrowB = wn * 64 + ((lane >> 4) << 3) + (lane & 7);
    const int bx    = nrowB & 7;
    const int cbit  = (lane >> 3) & 1;
    const uint32_t bRow = (uint32_t)nrowB * 128u + BMAT_OFF;

    int ph0 = 0, ph1 = 0;

    for (int ki = 0; ki < 8; ki++) {
        const int s = ki & 1;
        if (s == 0) { MBARRIER_WAIT_PARITY(sb + 0, ph0); ph0 ^= 1; }
        else        { MBARRIER_WAIT_PARITY(sb + 8, ph1); ph1 ^= 1; }

        const uint32_t st = stage0 + (uint32_t)s * STAGE_BYTES;

        #pragma unroll
        for (int kk = 0; kk < 4; kk++) {
            const int chA = kk * 2 + laneHi;          // 0..7
            const uint32_t slotA = (uint32_t)((chA ^ ax) << 4);
            uint32_t ah[4][4];
            #pragma unroll
            for (int i = 0; i < 4; i++)
                ldm4(ah[i], st + aRow + i * 2048 + slotA);

            const int chB = kk * 2 + cbit;            // 0..7
            const uint32_t slotB = (uint32_t)((chB ^ bx) << 4);
            #pragma unroll
            for (int jh = 0; jh < 2; jh++) {
                uint32_t bh[4][2];
                #pragma unroll
                for (int pp = 0; pp < 2; pp++) {
                    uint32_t tb[4];
                    ldm4(tb, st + bRow + (jh * 2 + pp) * 2048 + slotB);
                    bh[2 * pp][0] = tb[0]; bh[2 * pp][1] = tb[1];
                    bh[2 * pp + 1][0] = tb[2]; bh[2 * pp + 1][1] = tb[3];
                }
                #pragma unroll
                for (int i = 0; i < 4; i++)
                    #pragma unroll
                    for (int jj = 0; jj < 4; jj++)
                        mma16816(acc[i][jh * 4 + jj], ah[i], bh[jj][0], bh[jj][1]);
            }
        }

        __syncthreads();   // all warps done reading stage s
        if (ki + 2 < 8 && tid == 0) {
            const uint32_t mb = sb + (uint32_t)s * 8;
            MBARRIER_EXPECT_TX(mb, 2 * 16384);
            TMA_LOAD_2D(st,            &tmA, (ki + 2) * 64, m0, mb);
            TMA_LOAD_2D(st + BMAT_OFF, &tmB, (ki + 2) * 64, n0, mb);
        }
    }

    // ---- epilogue: margin, scale, store, partial expsum (poly exp, fma pipe)
    float es[4][2];
    #pragma unroll
    for (int i = 0; i < 4; i++) { es[i][0] = 0.f; es[i][1] = 0.f; }

    #pragma unroll
    for (int i = 0; i < 4; i++) {
        const int r0 = m0 + wm * 64 + i * 16 + (lane >> 2);
        const int r1 = r0 + 8;
        const int lab0 = g_label[r0];
        const int lab1 = g_label[r1];
        float* const o0 = out + (size_t)r0 * C_;
        float* const o1 = out + (size_t)r1 * C_;
        #pragma unroll
        for (int j = 0; j < 8; j++) {
            const int col = n0 + wn * 64 + j * 8 + (lane & 3) * 2;
            if (col < C_) {
                float2 v0, v1;
                float* p0 = (float*)&v0;
                float* p1 = (float*)&v1;
                #pragma unroll
                for (int q = 0; q < 2; q++) {
                    float c = acc[i][j][q];
                    if (col + q == lab0) {
                        float st2 = sqrtf(fmaxf(1.f - c * c, 0.f));
                        float phi = c * kCOS_M - st2 * kSIN_M;
                        c = (c - kTH > 0.f) ? phi : (c - kMM);
                    }
                    p0[q] = S_SCALE * c;
                    float d = acc[i][j][q + 2];
                    if (col + q == lab1) {
                        float st2 = sqrtf(fmaxf(1.f - d * d, 0.f));
                        float phi = d * kCOS_M - st2 * kSIN_M;
                        d = (d - kTH > 0.f) ? phi : (d - kMM);
                    }
                    p1[q] = S_SCALE * d;
                }
                __stcs(reinterpret_cast<float2*>(o0 + col), v0);
                __stcs(reinterpret_cast<float2*>(o1 + col), v1);
                es[i][0] += fexp_poly(p0[0]) + fexp_poly(p0[1]);
                es[i][1] += fexp_poly(p1[0]) + fexp_poly(p1[1]);
            }
        }
    }
    #pragma unroll
    for (int i = 0; i < 4; i++) {
        #pragma unroll
        for (int h = 0; h < 2; h++) {
            float v = es[i][h];
            v += __shfl_xor_sync(0xffffffffu, v, 1);
            v += __shfl_xor_sync(0xffffffffu, v, 2);
            if ((lane & 3) == 0) {
                const int r = m0 + wm * 64 + i * 16 + h * 8 + (lane >> 2);
                atomicAdd(&g_expsum[r], v);
            }
        }
    }
}

// ---------------- loss finalize (expsum accumulated in GEMM epilogue) -------
__global__ void finalize_kernel(float* __restrict__ out, int out_size) {
    __shared__ float red[256];
    float a = 0.f;
    for (int r = threadIdx.x; r < B_; r += 256) {
        float tgt = out[(size_t)r * C_ + g_label[r]];
        a += logf(g_expsum[r]) - tgt;
    }
    red[threadIdx.x] = a;
    __syncthreads();
    for (int s = 128; s > 0; s >>= 1) {
        if (threadIdx.x < s) red[threadIdx.x] += red[threadIdx.x + s];
        __syncthreads();
    }
    if (threadIdx.x == 0) {
        float loss = red[0] / (float)B_;
        for (long long i = (long long)B_ * C_; i < (long long)out_size; i++)
            out[i] = loss;
    }
}

// ---------------- host: tensor-map encode via driver entry point ------------
typedef CUresult (*tmap_encode_fn_t)(
    CUtensorMap*, CUtensorMapDataType, cuuint32_t, void*,
    const cuuint64_t*, const cuuint64_t*, const cuuint32_t*, const cuuint32_t*,
    CUtensorMapInterleave, CUtensorMapSwizzle, CUtensorMapL2promotion,
    CUtensorMapFloatOOBfill);

static tmap_encode_fn_t get_encode_fn() {
    void* fn = nullptr;
    cudaDriverEntryPointQueryResult qr;
#if CUDART_VERSION >= 12050
    cudaGetDriverEntryPointByVersion("cuTensorMapEncodeTiled", &fn, 12000,
                                     cudaEnableDefault, &qr);
#else
    cudaGetDriverEntryPoint("cuTensorMapEncodeTiled", &fn, cudaEnableDefault, &qr);
#endif
    return (tmap_encode_fn_t)fn;
}

static void encode_map(tmap_encode_fn_t enc, CUtensorMap* tm, void* base,
                       unsigned long long rows) {
    cuuint64_t dims[2]    = {(cuuint64_t)D_, (cuuint64_t)rows};
    cuuint64_t strides[1] = {(cuuint64_t)(D_ * 2)};      // 1024 B/row
    cuuint32_t box[2]     = {64, 128};                   // 128B x 128 rows
    cuuint32_t estr[2]    = {1, 1};
    enc(tm, CU_TENSOR_MAP_DATA_TYPE_FLOAT16, 2, base, dims, strides, box, estr,
        CU_TENSOR_MAP_INTERLEAVE_NONE, CU_TENSOR_MAP_SWIZZLE_128B,
        CU_TENSOR_MAP_L2_PROMOTION_L2_128B, CU_TENSOR_MAP_FLOAT_OOB_FILL_NONE);
}

// ---------------- launch ----------------
extern "C" void kernel_launch(void* const* d_in, const int* in_sizes, int n_in,
                              void* d_out, int out_size) {
    const float* x   = (const float*)d_in[0];
    const void*  lab = d_in[1];
    const float* w   = (const float*)d_in[2];
    float* out = (float*)d_out;

    cudaFuncSetAttribute(gemm_mma_kernel,
                         cudaFuncAttributeMaxDynamicSharedMemorySize, GEMM_SMEM);

    // tensor maps (host-side, deterministic, no allocation)
    tmap_encode_fn_t enc = get_encode_fn();
    void *dA = nullptr, *dB = nullptr;
    cudaGetSymbolAddress(&dA, g_xn);
    cudaGetSymbolAddress(&dB, g_wn);
    CUtensorMap tmA, tmB;
    encode_map(enc, &tmA, dA, B_);
    encode_map(enc, &tmB, dB, NPAD_);

    norm_x_kernel<<<B_ / 8, 256>>>(x, lab);   // also handles labels + expsum zero
    norm_w_kernel<<<NPAD_ / 8, 256>>>(w);

    dim3 grid(B_ / 128, NPAD_ / 128);   // (16, 391), m inner
    gemm_mma_kernel<<<grid, 128, GEMM_SMEM>>>(out, tmA, tmB);

    finalize_kernel<<<1, 256>>>(out, out_size);
}